// round 4
// baseline (speedup 1.0000x reference)
#include <cuda_runtime.h>

// Problem constants
#define NB 2
#define NS 2048
#define ND 1024
#define NH 16
#define NHD 64
#define NM (NB*NS)          // 4096 rows for all GEMMs
#define SCALE_F 0.125f      // 64^-0.5

// Scratch (alloc-free rule: __device__ globals)
__device__ float g_q[NB*NH*NS*NHD];
__device__ float g_k[NB*NH*NS*NHD];
__device__ float g_v[NB*NH*NS*NHD];
__device__ float g_att[NB*NS*ND];

// ---------------------------------------------------------------------------
// Tiled GEMM: C[M,N] = A[M,K] @ W[K,N] + bias[N]
// 64x64 block tile, BK=16, 256 threads, 4x4 per thread.
// SCATTER=true writes C in [B,H,S,HD] layout (fused head-split transpose).
// ---------------------------------------------------------------------------
template<bool SCATTER>
__global__ void __launch_bounds__(256)
gemm_bias(const float* __restrict__ A, const float* __restrict__ W,
          const float* __restrict__ bias, float* __restrict__ C,
          int M, int N, int K)
{
    __shared__ float sA[16][64];   // [k][m] (A transposed)
    __shared__ float sB[16][64];   // [k][n]

    const int tid = threadIdx.x;
    const int tx  = tid & 15;
    const int ty  = tid >> 4;
    const int m0  = blockIdx.y * 64;
    const int n0  = blockIdx.x * 64;

    // load mapping (A panel is 64 rows x 16 cols; B panel 16 x 64)
    const int arow = tid >> 2;          // 0..63
    const int ac   = (tid & 3) * 4;     // 0,4,8,12
    const int brow = tid >> 4;          // 0..15
    const int bc   = (tid & 15) * 4;    // 0..60

    const float* Ag = A + (size_t)(m0 + arow) * K + ac;
    const float* Wg = W + (size_t)brow * N + n0 + bc;

    float acc[4][4] = {};

    for (int k0 = 0; k0 < K; k0 += 16) {
        float4 av = *reinterpret_cast<const float4*>(Ag + k0);
        float4 bv = *reinterpret_cast<const float4*>(Wg + (size_t)k0 * N);
        __syncthreads();
        sA[ac+0][arow] = av.x;
        sA[ac+1][arow] = av.y;
        sA[ac+2][arow] = av.z;
        sA[ac+3][arow] = av.w;
        *reinterpret_cast<float4*>(&sB[brow][bc]) = bv;
        __syncthreads();
        #pragma unroll
        for (int kk = 0; kk < 16; ++kk) {
            float4 a = *reinterpret_cast<const float4*>(&sA[kk][ty*4]);
            float4 b = *reinterpret_cast<const float4*>(&sB[kk][tx*4]);
            float ar[4] = {a.x, a.y, a.z, a.w};
            float br[4] = {b.x, b.y, b.z, b.w};
            #pragma unroll
            for (int i = 0; i < 4; ++i)
                #pragma unroll
                for (int j = 0; j < 4; ++j)
                    acc[i][j] = fmaf(ar[i], br[j], acc[i][j]);
        }
    }

    float bvals[4];
    #pragma unroll
    for (int j = 0; j < 4; ++j) bvals[j] = bias[n0 + tx*4 + j];

    #pragma unroll
    for (int i = 0; i < 4; ++i) {
        const int m = m0 + ty*4 + i;
        float4 out;
        out.x = acc[i][0] + bvals[0];
        out.y = acc[i][1] + bvals[1];
        out.z = acc[i][2] + bvals[2];
        out.w = acc[i][3] + bvals[3];
        if (SCATTER) {
            // m = b*NS + s ; col n = h*NHD + hd  (n0 multiple of 64, HD=64)
            const int b = m >> 11;          // / NS
            const int s = m & (NS - 1);
            const int h = n0 >> 6;          // / NHD
            const size_t idx = (((size_t)(b*NH + h))*NS + s)*NHD + tx*4;
            *reinterpret_cast<float4*>(C + idx) = out;
        } else {
            *reinterpret_cast<float4*>(C + (size_t)m*N + n0 + tx*4) = out;
        }
    }
}

// ---------------------------------------------------------------------------
// Flash attention, fp32, causal. One block per (b, h, 64-row q-tile).
// 64x64 K/V tiles, online softmax, P staged through the K SMEM buffer.
// FIX vs R2: tile loads now cover the full 64x64 tile (lr4/lc4 mapping,
// 4 row-passes of 16 rows x 64 cols), not the GEMM's 64x16 panel mapping.
// ---------------------------------------------------------------------------
__global__ void __launch_bounds__(256)
attn_kernel(const float* __restrict__ Q, const float* __restrict__ K,
            const float* __restrict__ V, float* __restrict__ O)
{
    __shared__ float sQ [64][64];   // [d][r]   (Q transposed, resident)
    __shared__ float sKP[64][64];   // K phase: [d][c];  P phase: [k][r]
    __shared__ float sV [64][64];   // [k][d]

    const int tid = threadIdx.x;
    const int tx  = tid & 15;
    const int ty  = tid >> 4;
    const int qi  = (NS/64 - 1) - blockIdx.x;   // biggest tiles scheduled first
    const int h   = blockIdx.y;
    const int b   = blockIdx.z;
    const int bh  = b*NH + h;

    const float* Qb = Q + (size_t)bh * NS * NHD;
    const float* Kb = K + (size_t)bh * NS * NHD;
    const float* Vb = V + (size_t)bh * NS * NHD;

    // 64x64 tile load mapping: 16 rows per pass x 64 cols, 4 passes
    const int lr4 = tid >> 4;        // 0..15
    const int lc4 = (tid & 15) * 4;  // 0..60

    {   // load Q tile (transposed into [d][r]) — full 64x64 coverage
        #pragma unroll
        for (int rr = 0; rr < 64; rr += 16) {
            const int r = lr4 + rr;
            float4 qv = *reinterpret_cast<const float4*>(
                Qb + (size_t)(qi*64 + r)*NHD + lc4);
            sQ[lc4+0][r] = qv.x;
            sQ[lc4+1][r] = qv.y;
            sQ[lc4+2][r] = qv.z;
            sQ[lc4+3][r] = qv.w;
        }
    }

    float o[4][4]  = {};
    float mrow[4]  = {-1e30f, -1e30f, -1e30f, -1e30f};
    float lrow[4]  = {};
    const int qrow0 = qi*64 + ty*4;

    for (int j = 0; j <= qi; ++j) {
        // prefetch K/V tile to regs (before sync: no smem hazard)
        float4 kreg[4], vreg[4];
        #pragma unroll
        for (int p = 0; p < 4; ++p) {
            const int r = lr4 + p*16;
            kreg[p] = *reinterpret_cast<const float4*>(
                Kb + (size_t)(j*64 + r)*NHD + lc4);
            vreg[p] = *reinterpret_cast<const float4*>(
                Vb + (size_t)(j*64 + r)*NHD + lc4);
        }

        __syncthreads();                 // prior PV done reading sKP/sV
        #pragma unroll
        for (int p = 0; p < 4; ++p) {
            const int r = lr4 + p*16;
            sKP[lc4+0][r] = kreg[p].x;   // K transposed: [d][c]
            sKP[lc4+1][r] = kreg[p].y;
            sKP[lc4+2][r] = kreg[p].z;
            sKP[lc4+3][r] = kreg[p].w;
            *reinterpret_cast<float4*>(&sV[r][lc4]) = vreg[p];
        }
        __syncthreads();

        // S = Q @ K^T  (contraction over d)
        float acc[4][4] = {};
        #pragma unroll 8
        for (int d = 0; d < 64; ++d) {
            float4 a = *reinterpret_cast<const float4*>(&sQ [d][ty*4]);
            float4 c = *reinterpret_cast<const float4*>(&sKP[d][tx*4]);
            float ar[4] = {a.x, a.y, a.z, a.w};
            float cr[4] = {c.x, c.y, c.z, c.w};
            #pragma unroll
            for (int i = 0; i < 4; ++i)
                #pragma unroll
                for (int jj = 0; jj < 4; ++jj)
                    acc[i][jj] = fmaf(ar[i], cr[jj], acc[i][jj]);
        }

        // online softmax (row stats reduced across tx via shuffle;
        // offsets 1,2,4,8 stay within each 16-lane half-warp = one ty group)
        const bool diag = (j == qi);
        const int  kb   = j*64 + tx*4;
        #pragma unroll
        for (int i = 0; i < 4; ++i) {
            const int qrow = qrow0 + i;
            float mx = -1e30f;
            #pragma unroll
            for (int jj = 0; jj < 4; ++jj) {
                float sv = acc[i][jj] * SCALE_F;
                if (diag && (kb + jj > qrow)) sv = -1e30f;
                acc[i][jj] = sv;
                mx = fmaxf(mx, sv);
            }
            #pragma unroll
            for (int off = 1; off < 16; off <<= 1)
                mx = fmaxf(mx, __shfl_xor_sync(0xffffffffu, mx, off));
            const float mnew  = fmaxf(mrow[i], mx);
            const float alpha = __expf(mrow[i] - mnew);
            mrow[i] = mnew;
            float ls = 0.f;
            #pragma unroll
            for (int jj = 0; jj < 4; ++jj) {
                float p = __expf(acc[i][jj] - mnew);
                acc[i][jj] = p;
                ls += p;
            }
            #pragma unroll
            for (int off = 1; off < 16; off <<= 1)
                ls += __shfl_xor_sync(0xffffffffu, ls, off);
            lrow[i] = lrow[i]*alpha + ls;
            #pragma unroll
            for (int jo = 0; jo < 4; ++jo) o[i][jo] *= alpha;
        }

        __syncthreads();                 // all done reading sKP as K
        #pragma unroll
        for (int i = 0; i < 4; ++i)
            #pragma unroll
            for (int jj = 0; jj < 4; ++jj)
                sKP[tx*4 + jj][ty*4 + i] = acc[i][jj];   // P transposed: [k][r]
        __syncthreads();

        // O += P @ V  (contraction over k)
        #pragma unroll 8
        for (int kk = 0; kk < 64; ++kk) {
            float4 p = *reinterpret_cast<const float4*>(&sKP[kk][ty*4]);
            float4 v = *reinterpret_cast<const float4*>(&sV [kk][tx*4]);
            float pr[4] = {p.x, p.y, p.z, p.w};
            float vr[4] = {v.x, v.y, v.z, v.w};
            #pragma unroll
            for (int i = 0; i < 4; ++i)
                #pragma unroll
                for (int jj = 0; jj < 4; ++jj)
                    o[i][jj] = fmaf(pr[i], vr[jj], o[i][jj]);
        }
    }

    // epilogue: normalize, write back in [B,S,D] layout
    #pragma unroll
    for (int i = 0; i < 4; ++i) {
        const float inv = 1.0f / lrow[i];
        const int row = qrow0 + i;
        float4 out;
        out.x = o[i][0]*inv;
        out.y = o[i][1]*inv;
        out.z = o[i][2]*inv;
        out.w = o[i][3]*inv;
        const size_t idx = ((size_t)b*NS + row)*ND + h*NHD + tx*4;
        *reinterpret_cast<float4*>(O + idx) = out;
    }
}

// ---------------------------------------------------------------------------
extern "C" void kernel_launch(void* const* d_in, const int* in_sizes, int n_in,
                              void* d_out, int out_size)
{
    const float* x  = (const float*)d_in[0];
    const float* wq = (const float*)d_in[1];
    const float* bq = (const float*)d_in[2];
    const float* wk = (const float*)d_in[3];
    const float* bk = (const float*)d_in[4];
    const float* wv = (const float*)d_in[5];
    const float* bv = (const float*)d_in[6];
    const float* wo = (const float*)d_in[7];
    const float* bo = (const float*)d_in[8];
    float* out = (float*)d_out;

    float *q, *k, *v, *att;
    cudaGetSymbolAddress((void**)&q,   g_q);
    cudaGetSymbolAddress((void**)&k,   g_k);
    cudaGetSymbolAddress((void**)&v,   g_v);
    cudaGetSymbolAddress((void**)&att, g_att);

    dim3 ggrid(ND/64, NM/64);   // (16, 64)
    gemm_bias<true ><<<ggrid, 256>>>(x,   wq, bq, q,   NM, ND, ND);
    gemm_bias<true ><<<ggrid, 256>>>(x,   wk, bk, k,   NM, ND, ND);
    gemm_bias<true ><<<ggrid, 256>>>(x,   wv, bv, v,   NM, ND, ND);

    dim3 agrid(NS/64, NH, NB);  // (32, 16, 2)
    attn_kernel<<<agrid, 256>>>(q, k, v, att);

    gemm_bias<false><<<ggrid, 256>>>(att, wo, bo, out, NM, ND, ND);
}

// round 6
// speedup vs baseline: 1.6007x; 1.6007x over previous
#include <cuda_runtime.h>
#include <cstdint>

// Problem constants
#define NB 2
#define NS 2048
#define ND 1024
#define NH 16
#define NHD 64
#define NM (NB*NS)          // 4096 rows for all GEMMs
#define SCALE_F 0.125f      // 64^-0.5

// Scratch (alloc-free rule: __device__ globals)
__device__ float g_q[NB*NH*NS*NHD];
__device__ float g_k[NB*NH*NS*NHD];
__device__ float g_v[NB*NH*NS*NHD];
__device__ float g_att[NB*NS*ND];

// ---------------------------------------------------------------------------
__device__ __forceinline__ uint32_t cvt_tf32(float f) {
    uint32_t r;
    asm("cvt.rna.tf32.f32 %0, %1;" : "=r"(r) : "f"(f));
    return r;
}

__device__ __forceinline__ void mma_tf32(float c[4],
                                         uint32_t a0, uint32_t a1,
                                         uint32_t a2, uint32_t a3,
                                         uint32_t b0, uint32_t b1) {
    asm volatile(
        "mma.sync.aligned.m16n8k8.row.col.f32.tf32.tf32.f32 "
        "{%0,%1,%2,%3}, {%4,%5,%6,%7}, {%8,%9}, {%0,%1,%2,%3};"
        : "+f"(c[0]), "+f"(c[1]), "+f"(c[2]), "+f"(c[3])
        : "r"(a0), "r"(a1), "r"(a2), "r"(a3), "r"(b0), "r"(b1));
}

// ---------------------------------------------------------------------------
// tf32 mma.sync GEMM: C[4096,1024] = A @ W[1024,1024] + bias
// CTA 128x128, BK=32, 8 warps (2 M x 4 N), warp tile 64x32.
// SCATTER=true writes [B,H,S,HD] (fused head-split transpose).
// ---------------------------------------------------------------------------
#define SSTR 36   // padded smem stride (floats)

template<bool SCATTER>
__global__ void __launch_bounds__(256)
gemm_tc(const float* __restrict__ A, const float* __restrict__ W,
        const float* __restrict__ bias, float* __restrict__ C)
{
    constexpr int N = ND, K = ND;
    constexpr int BK = 32;
    constexpr int NCHUNK = K / BK;   // 32

    __shared__ uint32_t sA[128 * SSTR];   // [m][k] tf32 bits
    __shared__ uint32_t sB[128 * SSTR];   // [n][k] tf32 bits (W transposed)

    const int tid  = threadIdx.x;
    const int wid  = tid >> 5;
    const int lane = tid & 31;
    const int m0   = blockIdx.y * 128;
    const int n0   = blockIdx.x * 128;

    const int wm = (wid >> 2) * 64;   // warp M offset: 0 or 64
    const int wn = (wid & 3)  * 32;   // warp N offset: 0,32,64,96

    // gmem load mapping
    //  A: 128 rows x 32 k = 4 float4/thread
    //  B: col nloc of W, 16 k's (coalesced across 128 threads)
    const int nloc = tid & 127;
    const int kb   = (tid >> 7) * 16;   // 0 or 16

    float4 a_pf[4];
    float  b_pf[16];
    {   // prefetch chunk 0
        #pragma unroll
        for (int i = 0; i < 4; ++i) {
            int lin = tid + 256*i;
            int r = lin >> 3, j = lin & 7;
            a_pf[i] = *reinterpret_cast<const float4*>(
                A + (size_t)(m0 + r) * K + j * 4);
        }
        #pragma unroll
        for (int i = 0; i < 16; ++i)
            b_pf[i] = W[(size_t)(kb + i) * N + n0 + nloc];
    }

    float acc[16][4];
    #pragma unroll
    for (int t = 0; t < 16; ++t)
        #pragma unroll
        for (int e = 0; e < 4; ++e) acc[t][e] = 0.f;

    const int qrow = lane >> 2;   // 0..7
    const int qcol = lane & 3;    // 0..3

    for (int c = 0; c < NCHUNK; ++c) {
        if (c > 0) __syncthreads();          // mma phase done reading smem

        // ---- STS chunk c (convert to tf32) ----
        #pragma unroll
        for (int i = 0; i < 4; ++i) {
            int lin = tid + 256*i;
            int r = lin >> 3, j = lin & 7;
            uint4 t;
            t.x = cvt_tf32(a_pf[i].x);
            t.y = cvt_tf32(a_pf[i].y);
            t.z = cvt_tf32(a_pf[i].z);
            t.w = cvt_tf32(a_pf[i].w);
            *reinterpret_cast<uint4*>(&sA[r * SSTR + j * 4]) = t;
        }
        #pragma unroll
        for (int i = 0; i < 16; ++i)
            sB[nloc * SSTR + kb + i] = cvt_tf32(b_pf[i]);

        // ---- prefetch chunk c+1 (overlaps mma phase below) ----
        if (c + 1 < NCHUNK) {
            const int k0n = (c + 1) * BK;
            #pragma unroll
            for (int i = 0; i < 4; ++i) {
                int lin = tid + 256*i;
                int r = lin >> 3, j = lin & 7;
                a_pf[i] = *reinterpret_cast<const float4*>(
                    A + (size_t)(m0 + r) * K + k0n + j * 4);
            }
            #pragma unroll
            for (int i = 0; i < 16; ++i)
                b_pf[i] = W[(size_t)(k0n + kb + i) * N + n0 + nloc];
        }

        __syncthreads();

        // ---- 4 k-steps of m16n8k8 ----
        #pragma unroll
        for (int ks = 0; ks < 4; ++ks) {
            const int kbase = ks * 8 + qcol;
            uint32_t af[4][4];
            #pragma unroll
            for (int i = 0; i < 4; ++i) {
                const uint32_t* p = &sA[(wm + i*16 + qrow) * SSTR + kbase];
                af[i][0] = p[0];
                af[i][1] = p[8 * SSTR];
                af[i][2] = p[4];
                af[i][3] = p[8 * SSTR + 4];
            }
            uint32_t bf[4][2];
            #pragma unroll
            for (int j = 0; j < 4; ++j) {
                const uint32_t* p = &sB[(wn + j*8 + qrow) * SSTR + kbase];
                bf[j][0] = p[0];
                bf[j][1] = p[4];
            }
            #pragma unroll
            for (int i = 0; i < 4; ++i)
                #pragma unroll
                for (int j = 0; j < 4; ++j)
                    mma_tf32(acc[i*4 + j],
                             af[i][0], af[i][1], af[i][2], af[i][3],
                             bf[j][0], bf[j][1]);
        }
    }

    // ---- epilogue: bias + (optional) head-split scatter ----
    #pragma unroll
    for (int i = 0; i < 4; ++i) {
        #pragma unroll
        for (int j = 0; j < 4; ++j) {
            const float* a4 = acc[i*4 + j];
            const int colg  = n0 + wn + j*8 + 2*qcol;          // global col
            const float2 bv = *reinterpret_cast<const float2*>(bias + colg);
            #pragma unroll
            for (int half = 0; half < 2; ++half) {             // row, row+8
                const int m = m0 + wm + i*16 + qrow + half*8;
                float2 o;
                o.x = a4[half*2 + 0] + bv.x;
                o.y = a4[half*2 + 1] + bv.y;
                size_t idx;
                if (SCATTER) {
                    const int b = m >> 11;
                    const int s = m & (NS - 1);
                    const int h = colg >> 6;
                    const int hd = colg & 63;
                    idx = (((size_t)(b*NH + h))*NS + s)*NHD + hd;
                } else {
                    idx = (size_t)m * N + colg;
                }
                *reinterpret_cast<float2*>(C + idx) = o;
            }
        }
    }
}

// ---------------------------------------------------------------------------
// Flash attention, fp32, causal (unchanged from R3 — passing).
// ---------------------------------------------------------------------------
__global__ void __launch_bounds__(256)
attn_kernel(const float* __restrict__ Q, const float* __restrict__ K,
            const float* __restrict__ V, float* __restrict__ O)
{
    __shared__ float sQ [64][64];   // [d][r]   (Q transposed, resident)
    __shared__ float sKP[64][64];   // K phase: [d][c];  P phase: [k][r]
    __shared__ float sV [64][64];   // [k][d]

    const int tid = threadIdx.x;
    const int tx  = tid & 15;
    const int ty  = tid >> 4;
    const int qi  = (NS/64 - 1) - blockIdx.x;   // biggest tiles scheduled first
    const int h   = blockIdx.y;
    const int b   = blockIdx.z;
    const int bh  = b*NH + h;

    const float* Qb = Q + (size_t)bh * NS * NHD;
    const float* Kb = K + (size_t)bh * NS * NHD;
    const float* Vb = V + (size_t)bh * NS * NHD;

    const int lr4 = tid >> 4;        // 0..15
    const int lc4 = (tid & 15) * 4;  // 0..60

    {   // load Q tile (transposed into [d][r]) — full 64x64 coverage
        #pragma unroll
        for (int rr = 0; rr < 64; rr += 16) {
            const int r = lr4 + rr;
            float4 qv = *reinterpret_cast<const float4*>(
                Qb + (size_t)(qi*64 + r)*NHD + lc4);
            sQ[lc4+0][r] = qv.x;
            sQ[lc4+1][r] = qv.y;
            sQ[lc4+2][r] = qv.z;
            sQ[lc4+3][r] = qv.w;
        }
    }

    float o[4][4]  = {};
    float mrow[4]  = {-1e30f, -1e30f, -1e30f, -1e30f};
    float lrow[4]  = {};
    const int qrow0 = qi*64 + ty*4;

    for (int j = 0; j <= qi; ++j) {
        float4 kreg[4], vreg[4];
        #pragma unroll
        for (int p = 0; p < 4; ++p) {
            const int r = lr4 + p*16;
            kreg[p] = *reinterpret_cast<const float4*>(
                Kb + (size_t)(j*64 + r)*NHD + lc4);
            vreg[p] = *reinterpret_cast<const float4*>(
                Vb + (size_t)(j*64 + r)*NHD + lc4);
        }

        __syncthreads();
        #pragma unroll
        for (int p = 0; p < 4; ++p) {
            const int r = lr4 + p*16;
            sKP[lc4+0][r] = kreg[p].x;
            sKP[lc4+1][r] = kreg[p].y;
            sKP[lc4+2][r] = kreg[p].z;
            sKP[lc4+3][r] = kreg[p].w;
            *reinterpret_cast<float4*>(&sV[r][lc4]) = vreg[p];
        }
        __syncthreads();

        float acc[4][4] = {};
        #pragma unroll 8
        for (int d = 0; d < 64; ++d) {
            float4 a = *reinterpret_cast<const float4*>(&sQ [d][ty*4]);
            float4 c = *reinterpret_cast<const float4*>(&sKP[d][tx*4]);
            float ar[4] = {a.x, a.y, a.z, a.w};
            float cr[4] = {c.x, c.y, c.z, c.w};
            #pragma unroll
            for (int i = 0; i < 4; ++i)
                #pragma unroll
                for (int jj = 0; jj < 4; ++jj)
                    acc[i][jj] = fmaf(ar[i], cr[jj], acc[i][jj]);
        }

        const bool diag = (j == qi);
        const int  kbx  = j*64 + tx*4;
        #pragma unroll
        for (int i = 0; i < 4; ++i) {
            const int qrow = qrow0 + i;
            float mx = -1e30f;
            #pragma unroll
            for (int jj = 0; jj < 4; ++jj) {
                float sv = acc[i][jj] * SCALE_F;
                if (diag && (kbx + jj > qrow)) sv = -1e30f;
                acc[i][jj] = sv;
                mx = fmaxf(mx, sv);
            }
            #pragma unroll
            for (int off = 1; off < 16; off <<= 1)
                mx = fmaxf(mx, __shfl_xor_sync(0xffffffffu, mx, off));
            const float mnew  = fmaxf(mrow[i], mx);
            const float alpha = __expf(mrow[i] - mnew);
            mrow[i] = mnew;
            float ls = 0.f;
            #pragma unroll
            for (int jj = 0; jj < 4; ++jj) {
                float p = __expf(acc[i][jj] - mnew);
                acc[i][jj] = p;
                ls += p;
            }
            #pragma unroll
            for (int off = 1; off < 16; off <<= 1)
                ls += __shfl_xor_sync(0xffffffffu, ls, off);
            lrow[i] = lrow[i]*alpha + ls;
            #pragma unroll
            for (int jo = 0; jo < 4; ++jo) o[i][jo] *= alpha;
        }

        __syncthreads();
        #pragma unroll
        for (int i = 0; i < 4; ++i)
            #pragma unroll
            for (int jj = 0; jj < 4; ++jj)
                sKP[tx*4 + jj][ty*4 + i] = acc[i][jj];
        __syncthreads();

        #pragma unroll 8
        for (int kk = 0; kk < 64; ++kk) {
            float4 p = *reinterpret_cast<const float4*>(&sKP[kk][ty*4]);
            float4 v = *reinterpret_cast<const float4*>(&sV [kk][tx*4]);
            float pr[4] = {p.x, p.y, p.z, p.w};
            float vr[4] = {v.x, v.y, v.z, v.w};
            #pragma unroll
            for (int i = 0; i < 4; ++i)
                #pragma unroll
                for (int jj = 0; jj < 4; ++jj)
                    o[i][jj] = fmaf(pr[i], vr[jj], o[i][jj]);
        }
    }

    #pragma unroll
    for (int i = 0; i < 4; ++i) {
        const float inv = 1.0f / lrow[i];
        const int row = qrow0 + i;
        float4 out;
        out.x = o[i][0]*inv;
        out.y = o[i][1]*inv;
        out.z = o[i][2]*inv;
        out.w = o[i][3]*inv;
        const size_t idx = ((size_t)b*NS + row)*ND + h*NHD + tx*4;
        *reinterpret_cast<float4*>(O + idx) = out;
    }
}

// ---------------------------------------------------------------------------
extern "C" void kernel_launch(void* const* d_in, const int* in_sizes, int n_in,
                              void* d_out, int out_size)
{
    const float* x  = (const float*)d_in[0];
    const float* wq = (const float*)d_in[1];
    const float* bq = (const float*)d_in[2];
    const float* wk = (const float*)d_in[3];
    const float* bk = (const float*)d_in[4];
    const float* wv = (const float*)d_in[5];
    const float* bv = (const float*)d_in[6];
    const float* wo = (const float*)d_in[7];
    const float* bo = (const float*)d_in[8];
    float* out = (float*)d_out;

    float *q, *k, *v, *att;
    cudaGetSymbolAddress((void**)&q,   g_q);
    cudaGetSymbolAddress((void**)&k,   g_k);
    cudaGetSymbolAddress((void**)&v,   g_v);
    cudaGetSymbolAddress((void**)&att, g_att);

    dim3 ggrid(ND/128, NM/128);   // (8, 32) = 256 CTAs
    gemm_tc<true ><<<ggrid, 256>>>(x,   wq, bq, q);
    gemm_tc<true ><<<ggrid, 256>>>(x,   wk, bk, k);
    gemm_tc<true ><<<ggrid, 256>>>(x,   wv, bv, v);

    dim3 agrid(NS/64, NH, NB);    // (32, 16, 2)
    attn_kernel<<<agrid, 256>>>(q, k, v, att);

    gemm_tc<false><<<ggrid, 256>>>(att, wo, bo, out);
}

// round 7
// speedup vs baseline: 2.9398x; 1.8366x over previous
#include <cuda_runtime.h>
#include <cstdint>

// Problem constants
#define NB 2
#define NS 2048
#define ND 1024
#define NH 16
#define NHD 64
#define NM (NB*NS)
#define SCALE_F 0.125f      // 64^-0.5

// Scratch (alloc-free rule: __device__ globals)
__device__ float g_q[NB*NH*NS*NHD];
__device__ float g_k[NB*NH*NS*NHD];
__device__ float g_v[NB*NH*NS*NHD];
__device__ float g_att[NB*NS*ND];

// ---------------------------------------------------------------------------
__device__ __forceinline__ uint32_t cvt_tf32(float f) {
    uint32_t r;
    asm("cvt.rna.tf32.f32 %0, %1;" : "=r"(r) : "f"(f));
    return r;
}

__device__ __forceinline__ void mma_tf32(float c[4],
                                         uint32_t a0, uint32_t a1,
                                         uint32_t a2, uint32_t a3,
                                         uint32_t b0, uint32_t b1) {
    asm volatile(
        "mma.sync.aligned.m16n8k8.row.col.f32.tf32.tf32.f32 "
        "{%0,%1,%2,%3}, {%4,%5,%6,%7}, {%8,%9}, {%0,%1,%2,%3};"
        : "+f"(c[0]), "+f"(c[1]), "+f"(c[2]), "+f"(c[3])
        : "r"(a0), "r"(a1), "r"(a2), "r"(a3), "r"(b0), "r"(b1));
}

// ---------------------------------------------------------------------------
// tf32 mma.sync GEMM (unchanged from R5 — passing): C = A @ W + bias
// ---------------------------------------------------------------------------
#define SSTR 36

template<bool SCATTER>
__global__ void __launch_bounds__(256)
gemm_tc(const float* __restrict__ A, const float* __restrict__ W,
        const float* __restrict__ bias, float* __restrict__ C)
{
    constexpr int N = ND, K = ND;
    constexpr int BK = 32;
    constexpr int NCHUNK = K / BK;

    __shared__ uint32_t sA[128 * SSTR];
    __shared__ uint32_t sB[128 * SSTR];

    const int tid  = threadIdx.x;
    const int wid  = tid >> 5;
    const int lane = tid & 31;
    const int m0   = blockIdx.y * 128;
    const int n0   = blockIdx.x * 128;

    const int wm = (wid >> 2) * 64;
    const int wn = (wid & 3)  * 32;

    const int nloc = tid & 127;
    const int kb   = (tid >> 7) * 16;

    float4 a_pf[4];
    float  b_pf[16];
    {
        #pragma unroll
        for (int i = 0; i < 4; ++i) {
            int lin = tid + 256*i;
            int r = lin >> 3, j = lin & 7;
            a_pf[i] = *reinterpret_cast<const float4*>(
                A + (size_t)(m0 + r) * K + j * 4);
        }
        #pragma unroll
        for (int i = 0; i < 16; ++i)
            b_pf[i] = W[(size_t)(kb + i) * N + n0 + nloc];
    }

    float acc[16][4];
    #pragma unroll
    for (int t = 0; t < 16; ++t)
        #pragma unroll
        for (int e = 0; e < 4; ++e) acc[t][e] = 0.f;

    const int qrow = lane >> 2;
    const int qcol = lane & 3;

    for (int c = 0; c < NCHUNK; ++c) {
        if (c > 0) __syncthreads();

        #pragma unroll
        for (int i = 0; i < 4; ++i) {
            int lin = tid + 256*i;
            int r = lin >> 3, j = lin & 7;
            uint4 t;
            t.x = cvt_tf32(a_pf[i].x);
            t.y = cvt_tf32(a_pf[i].y);
            t.z = cvt_tf32(a_pf[i].z);
            t.w = cvt_tf32(a_pf[i].w);
            *reinterpret_cast<uint4*>(&sA[r * SSTR + j * 4]) = t;
        }
        #pragma unroll
        for (int i = 0; i < 16; ++i)
            sB[nloc * SSTR + kb + i] = cvt_tf32(b_pf[i]);

        if (c + 1 < NCHUNK) {
            const int k0n = (c + 1) * BK;
            #pragma unroll
            for (int i = 0; i < 4; ++i) {
                int lin = tid + 256*i;
                int r = lin >> 3, j = lin & 7;
                a_pf[i] = *reinterpret_cast<const float4*>(
                    A + (size_t)(m0 + r) * K + k0n + j * 4);
            }
            #pragma unroll
            for (int i = 0; i < 16; ++i)
                b_pf[i] = W[(size_t)(k0n + kb + i) * N + n0 + nloc];
        }

        __syncthreads();

        #pragma unroll
        for (int ks = 0; ks < 4; ++ks) {
            const int kbase = ks * 8 + qcol;
            uint32_t af[4][4];
            #pragma unroll
            for (int i = 0; i < 4; ++i) {
                const uint32_t* p = &sA[(wm + i*16 + qrow) * SSTR + kbase];
                af[i][0] = p[0];
                af[i][1] = p[8 * SSTR];
                af[i][2] = p[4];
                af[i][3] = p[8 * SSTR + 4];
            }
            uint32_t bf[4][2];
            #pragma unroll
            for (int j = 0; j < 4; ++j) {
                const uint32_t* p = &sB[(wn + j*8 + qrow) * SSTR + kbase];
                bf[j][0] = p[0];
                bf[j][1] = p[4];
            }
            #pragma unroll
            for (int i = 0; i < 4; ++i)
                #pragma unroll
                for (int j = 0; j < 4; ++j)
                    mma_tf32(acc[i*4 + j],
                             af[i][0], af[i][1], af[i][2], af[i][3],
                             bf[j][0], bf[j][1]);
        }
    }

    #pragma unroll
    for (int i = 0; i < 4; ++i) {
        #pragma unroll
        for (int j = 0; j < 4; ++j) {
            const float* a4 = acc[i*4 + j];
            const int colg  = n0 + wn + j*8 + 2*qcol;
            const float2 bv = *reinterpret_cast<const float2*>(bias + colg);
            #pragma unroll
            for (int half = 0; half < 2; ++half) {
                const int m = m0 + wm + i*16 + qrow + half*8;
                float2 o;
                o.x = a4[half*2 + 0] + bv.x;
                o.y = a4[half*2 + 1] + bv.y;
                size_t idx;
                if (SCATTER) {
                    const int b = m >> 11;
                    const int s = m & (NS - 1);
                    const int h = colg >> 6;
                    const int hd = colg & 63;
                    idx = (((size_t)(b*NH + h))*NS + s)*NHD + hd;
                } else {
                    idx = (size_t)m * N + colg;
                }
                *reinterpret_cast<float2*>(C + idx) = o;
            }
        }
    }
}

// ---------------------------------------------------------------------------
// Tensor-core flash attention (tf32 mma.sync), causal.
// CTA = (b, h, 128-row Q tile), 8 warps, warp owns 16 rows x full 64 key cols.
// QK^T uses 2-term K hi/lo split for near-fp32 score accuracy.
// P routed through per-warp smem staging (syncwarp only).
// Dynamic smem: 105472 B -> occ 2.
// ---------------------------------------------------------------------------
// smem layout (uint32 words)
#define AQ_STR   68
#define AP_STR   36
#define OFF_Q    0              // 128*68 = 8704
#define OFF_KHI  8704           // 64*68  = 4352
#define OFF_KLO  13056          // 64*68  = 4352
#define OFF_VT   17408          // 64*68  = 4352
#define OFF_P    21760          // 8*16*36 = 4608
#define SMEM_WORDS 26368        // *4 = 105472 B

__global__ void __launch_bounds__(256)
attn_tc(const float* __restrict__ Q, const float* __restrict__ K,
        const float* __restrict__ V, float* __restrict__ O)
{
    extern __shared__ uint32_t sm[];
    uint32_t* sQ   = sm + OFF_Q;
    uint32_t* sKhi = sm + OFF_KHI;
    uint32_t* sKlo = sm + OFF_KLO;
    uint32_t* sVt  = sm + OFF_VT;

    const int tid  = threadIdx.x;
    const int wid  = tid >> 5;
    const int lane = tid & 31;
    const int qrow = lane >> 2;   // 0..7
    const int qcol = lane & 3;    // 0..3
    const int wm   = wid * 16;    // warp's row base within the 128-row tile

    const int qt = (NS/128 - 1) - blockIdx.x;   // largest-work tiles first
    const int h  = blockIdx.y;
    const int b  = blockIdx.z;
    const int bh = b*NH + h;

    const float* Qb = Q + (size_t)bh * NS * NHD;
    const float* Kb = K + (size_t)bh * NS * NHD;
    const float* Vb = V + (size_t)bh * NS * NHD;

    // ---- load Q tile (rows qt*128..+127) as tf32, [row][d] ----
    #pragma unroll
    for (int p = 0; p < 8; ++p) {
        int lin = tid + 256*p;
        int r = lin >> 4, c = (lin & 15) * 4;
        float4 qv = *reinterpret_cast<const float4*>(
            Qb + (size_t)(qt*128 + r)*NHD + c);
        uint32_t* d = &sQ[r * AQ_STR + c];
        d[0] = cvt_tf32(qv.x);
        d[1] = cvt_tf32(qv.y);
        d[2] = cvt_tf32(qv.z);
        d[3] = cvt_tf32(qv.w);
    }

    float o[8][4];
    #pragma unroll
    for (int nt = 0; nt < 8; ++nt)
        #pragma unroll
        for (int e = 0; e < 4; ++e) o[nt][e] = 0.f;
    float mrow[2] = {-1e30f, -1e30f};
    float lrow[2] = {0.f, 0.f};

    // V-transpose load mapping: thread owns one key column, 16 d's
    const int vkey = tid & 63;
    const int vdg  = (tid >> 6) * 16;

    const int jmax = 2*qt + 1;
    for (int j = 0; j <= jmax; ++j) {
        __syncthreads();   // previous iteration done with sKhi/sKlo/sVt

        // ---- stage K tile (hi/lo tf32 split), [key][d] ----
        #pragma unroll
        for (int p = 0; p < 4; ++p) {
            int lin = tid + 256*p;
            int r = lin >> 4, c = (lin & 15) * 4;
            float4 kv = *reinterpret_cast<const float4*>(
                Kb + (size_t)(j*64 + r)*NHD + c);
            uint32_t* dh = &sKhi[r * AQ_STR + c];
            uint32_t* dl = &sKlo[r * AQ_STR + c];
            float f[4] = {kv.x, kv.y, kv.z, kv.w};
            #pragma unroll
            for (int e = 0; e < 4; ++e) {
                uint32_t hi = cvt_tf32(f[e]);
                dh[e] = hi;
                dl[e] = cvt_tf32(f[e] - __uint_as_float(hi));
            }
        }

        // ---- stage V tile transposed: sVt[d][key] ----
        {
            const float* vp = Vb + (size_t)(j*64 + vkey)*NHD + vdg;
            #pragma unroll
            for (int g = 0; g < 4; ++g) {
                float4 vv = *reinterpret_cast<const float4*>(vp + g*4);
                float f[4] = {vv.x, vv.y, vv.z, vv.w};
                #pragma unroll
                for (int e = 0; e < 4; ++e)
                    sVt[(vdg + g*4 + e) * AQ_STR + vkey] = cvt_tf32(f[e]);
            }
        }
        __syncthreads();

        // ---- S = Q @ K^T (2-term: q_hi*k_hi + q_hi*k_lo) ----
        float s[8][4];
        #pragma unroll
        for (int nt = 0; nt < 8; ++nt)
            #pragma unroll
            for (int e = 0; e < 4; ++e) s[nt][e] = 0.f;

        #pragma unroll
        for (int ks = 0; ks < 8; ++ks) {
            const uint32_t* qp = &sQ[(wm + qrow) * AQ_STR + ks*8 + qcol];
            uint32_t a0 = qp[0], a1 = qp[8*AQ_STR], a2 = qp[4], a3 = qp[8*AQ_STR + 4];
            #pragma unroll
            for (int nt = 0; nt < 8; ++nt) {
                const int off = (nt*8 + qrow) * AQ_STR + ks*8 + qcol;
                mma_tf32(s[nt], a0, a1, a2, a3, sKhi[off], sKhi[off + 4]);
                mma_tf32(s[nt], a0, a1, a2, a3, sKlo[off], sKlo[off + 4]);
            }
        }

        // ---- online softmax (per lane: 2 rows) ----
        const bool need_mask = (j >= 2*qt);
        #pragma unroll
        for (int r = 0; r < 2; ++r) {
            const int rowg = qt*128 + wm + qrow + r*8;
            float mx = -1e30f;
            #pragma unroll
            for (int nt = 0; nt < 8; ++nt) {
                const int colg = j*64 + nt*8 + 2*qcol;
                float v0 = s[nt][r*2 + 0] * SCALE_F;
                float v1 = s[nt][r*2 + 1] * SCALE_F;
                if (need_mask) {
                    if (colg     > rowg) v0 = -1e30f;
                    if (colg + 1 > rowg) v1 = -1e30f;
                }
                s[nt][r*2 + 0] = v0;
                s[nt][r*2 + 1] = v1;
                mx = fmaxf(mx, fmaxf(v0, v1));
            }
            mx = fmaxf(mx, __shfl_xor_sync(0xffffffffu, mx, 1));
            mx = fmaxf(mx, __shfl_xor_sync(0xffffffffu, mx, 2));
            const float mn    = fmaxf(mrow[r], mx);
            const float alpha = __expf(mrow[r] - mn);
            mrow[r] = mn;
            float ls = 0.f;
            #pragma unroll
            for (int nt = 0; nt < 8; ++nt) {
                float p0 = __expf(s[nt][r*2 + 0] - mn);
                float p1 = __expf(s[nt][r*2 + 1] - mn);
                s[nt][r*2 + 0] = p0;
                s[nt][r*2 + 1] = p1;
                ls += p0 + p1;
            }
            ls += __shfl_xor_sync(0xffffffffu, ls, 1);
            ls += __shfl_xor_sync(0xffffffffu, ls, 2);
            lrow[r] = lrow[r]*alpha + ls;
            #pragma unroll
            for (int nt = 0; nt < 8; ++nt) {
                o[nt][r*2 + 0] *= alpha;
                o[nt][r*2 + 1] *= alpha;
            }
        }

        // ---- O += P @ V via per-warp staging (two 32-key halves) ----
        uint32_t* sPw = sm + OFF_P + wid * (16 * AP_STR);
        #pragma unroll
        for (int kh = 0; kh < 2; ++kh) {
            __syncwarp();
            #pragma unroll
            for (int t = 0; t < 4; ++t) {
                const int nt = kh*4 + t;
                const int lc = t*8 + 2*qcol;
                sPw[qrow * AP_STR + lc]           = cvt_tf32(s[nt][0]);
                sPw[qrow * AP_STR + lc + 1]       = cvt_tf32(s[nt][1]);
                sPw[(qrow + 8) * AP_STR + lc]     = cvt_tf32(s[nt][2]);
                sPw[(qrow + 8) * AP_STR + lc + 1] = cvt_tf32(s[nt][3]);
            }
            __syncwarp();
            #pragma unroll
            for (int ks = 0; ks < 4; ++ks) {
                const uint32_t* p0 = &sPw[qrow * AP_STR + ks*8 + qcol];
                const uint32_t* p1 = &sPw[(qrow + 8) * AP_STR + ks*8 + qcol];
                uint32_t a0 = p0[0], a1 = p1[0], a2 = p0[4], a3 = p1[4];
                #pragma unroll
                for (int nt = 0; nt < 8; ++nt) {
                    const int off = (nt*8 + qrow) * AQ_STR + kh*32 + ks*8 + qcol;
                    mma_tf32(o[nt], a0, a1, a2, a3, sVt[off], sVt[off + 4]);
                }
            }
        }
    }

    // ---- normalize + write [B,S,D] ----
    #pragma unroll
    for (int r = 0; r < 2; ++r) {
        const float inv = 1.0f / lrow[r];
        const int rowg = qt*128 + wm + qrow + r*8;
        #pragma unroll
        for (int nt = 0; nt < 8; ++nt) {
            const int col = h*NHD + nt*8 + 2*qcol;
            float2 ov;
            ov.x = o[nt][r*2 + 0] * inv;
            ov.y = o[nt][r*2 + 1] * inv;
            *reinterpret_cast<float2*>(
                O + ((size_t)b*NS + rowg)*ND + col) = ov;
        }
    }
}

// ---------------------------------------------------------------------------
extern "C" void kernel_launch(void* const* d_in, const int* in_sizes, int n_in,
                              void* d_out, int out_size)
{
    const float* x  = (const float*)d_in[0];
    const float* wq = (const float*)d_in[1];
    const float* bq = (const float*)d_in[2];
    const float* wk = (const float*)d_in[3];
    const float* bk = (const float*)d_in[4];
    const float* wv = (const float*)d_in[5];
    const float* bv = (const float*)d_in[6];
    const float* wo = (const float*)d_in[7];
    const float* bo = (const float*)d_in[8];
    float* out = (float*)d_out;

    float *q, *k, *v, *att;
    cudaGetSymbolAddress((void**)&q,   g_q);
    cudaGetSymbolAddress((void**)&k,   g_k);
    cudaGetSymbolAddress((void**)&v,   g_v);
    cudaGetSymbolAddress((void**)&att, g_att);

    static bool attr_done = false;
    if (!attr_done) {
        cudaFuncSetAttribute(attn_tc,
            cudaFuncAttributeMaxDynamicSharedMemorySize, SMEM_WORDS * 4);
        attr_done = true;
    }

    dim3 ggrid(ND/128, NM/128);   // (8, 32)
    gemm_tc<true ><<<ggrid, 256>>>(x,   wq, bq, q);
    gemm_tc<true ><<<ggrid, 256>>>(x,   wk, bk, k);
    gemm_tc<true ><<<ggrid, 256>>>(x,   wv, bv, v);

    dim3 agrid(NS/128, NH, NB);   // (16, 16, 2)
    attn_tc<<<agrid, 256, SMEM_WORDS * 4>>>(q, k, v, att);

    gemm_tc<false><<<ggrid, 256>>>(att, wo, bo, out);
}

// round 8
// speedup vs baseline: 3.2840x; 1.1171x over previous
#include <cuda_runtime.h>
#include <cstdint>

// Problem constants
#define NB 2
#define NS 2048
#define ND 1024
#define NH 16
#define NHD 64
#define NM (NB*NS)
#define SCALE_F 0.125f      // 64^-0.5

// Scratch (alloc-free rule: __device__ globals)
__device__ float g_q[NB*NH*NS*NHD];
__device__ float g_k[NB*NH*NS*NHD];
__device__ float g_v[NB*NH*NS*NHD];
__device__ float g_att[NB*NS*ND];

// ---------------------------------------------------------------------------
__device__ __forceinline__ uint32_t cvt_tf32(float f) {
    uint32_t r;
    asm("cvt.rna.tf32.f32 %0, %1;" : "=r"(r) : "f"(f));
    return r;
}

__device__ __forceinline__ void mma_tf32(float c[4],
                                         uint32_t a0, uint32_t a1,
                                         uint32_t a2, uint32_t a3,
                                         uint32_t b0, uint32_t b1) {
    asm volatile(
        "mma.sync.aligned.m16n8k8.row.col.f32.tf32.tf32.f32 "
        "{%0,%1,%2,%3}, {%4,%5,%6,%7}, {%8,%9}, {%0,%1,%2,%3};"
        : "+f"(c[0]), "+f"(c[1]), "+f"(c[2]), "+f"(c[3])
        : "r"(a0), "r"(a1), "r"(a2), "r"(a3), "r"(b0), "r"(b1));
}

// ---------------------------------------------------------------------------
// tf32 mma.sync GEMM (unchanged from R5/R6 — passing): C = A @ W + bias
// ---------------------------------------------------------------------------
#define SSTR 36

template<bool SCATTER>
__global__ void __launch_bounds__(256)
gemm_tc(const float* __restrict__ A, const float* __restrict__ W,
        const float* __restrict__ bias, float* __restrict__ C)
{
    constexpr int N = ND, K = ND;
    constexpr int BK = 32;
    constexpr int NCHUNK = K / BK;

    __shared__ uint32_t sA[128 * SSTR];
    __shared__ uint32_t sB[128 * SSTR];

    const int tid  = threadIdx.x;
    const int wid  = tid >> 5;
    const int lane = tid & 31;
    const int m0   = blockIdx.y * 128;
    const int n0   = blockIdx.x * 128;

    const int wm = (wid >> 2) * 64;
    const int wn = (wid & 3)  * 32;

    const int nloc = tid & 127;
    const int kb   = (tid >> 7) * 16;

    float4 a_pf[4];
    float  b_pf[16];
    {
        #pragma unroll
        for (int i = 0; i < 4; ++i) {
            int lin = tid + 256*i;
            int r = lin >> 3, j = lin & 7;
            a_pf[i] = *reinterpret_cast<const float4*>(
                A + (size_t)(m0 + r) * K + j * 4);
        }
        #pragma unroll
        for (int i = 0; i < 16; ++i)
            b_pf[i] = W[(size_t)(kb + i) * N + n0 + nloc];
    }

    float acc[16][4];
    #pragma unroll
    for (int t = 0; t < 16; ++t)
        #pragma unroll
        for (int e = 0; e < 4; ++e) acc[t][e] = 0.f;

    const int qrow = lane >> 2;
    const int qcol = lane & 3;

    for (int c = 0; c < NCHUNK; ++c) {
        if (c > 0) __syncthreads();

        #pragma unroll
        for (int i = 0; i < 4; ++i) {
            int lin = tid + 256*i;
            int r = lin >> 3, j = lin & 7;
            uint4 t;
            t.x = cvt_tf32(a_pf[i].x);
            t.y = cvt_tf32(a_pf[i].y);
            t.z = cvt_tf32(a_pf[i].z);
            t.w = cvt_tf32(a_pf[i].w);
            *reinterpret_cast<uint4*>(&sA[r * SSTR + j * 4]) = t;
        }
        #pragma unroll
        for (int i = 0; i < 16; ++i)
            sB[nloc * SSTR + kb + i] = cvt_tf32(b_pf[i]);

        if (c + 1 < NCHUNK) {
            const int k0n = (c + 1) * BK;
            #pragma unroll
            for (int i = 0; i < 4; ++i) {
                int lin = tid + 256*i;
                int r = lin >> 3, j = lin & 7;
                a_pf[i] = *reinterpret_cast<const float4*>(
                    A + (size_t)(m0 + r) * K + k0n + j * 4);
            }
            #pragma unroll
            for (int i = 0; i < 16; ++i)
                b_pf[i] = W[(size_t)(k0n + kb + i) * N + n0 + nloc];
        }

        __syncthreads();

        #pragma unroll
        for (int ks = 0; ks < 4; ++ks) {
            const int kbase = ks * 8 + qcol;
            uint32_t af[4][4];
            #pragma unroll
            for (int i = 0; i < 4; ++i) {
                const uint32_t* p = &sA[(wm + i*16 + qrow) * SSTR + kbase];
                af[i][0] = p[0];
                af[i][1] = p[8 * SSTR];
                af[i][2] = p[4];
                af[i][3] = p[8 * SSTR + 4];
            }
            uint32_t bf[4][2];
            #pragma unroll
            for (int j = 0; j < 4; ++j) {
                const uint32_t* p = &sB[(wn + j*8 + qrow) * SSTR + kbase];
                bf[j][0] = p[0];
                bf[j][1] = p[4];
            }
            #pragma unroll
            for (int i = 0; i < 4; ++i)
                #pragma unroll
                for (int j = 0; j < 4; ++j)
                    mma_tf32(acc[i*4 + j],
                             af[i][0], af[i][1], af[i][2], af[i][3],
                             bf[j][0], bf[j][1]);
        }
    }

    #pragma unroll
    for (int i = 0; i < 4; ++i) {
        #pragma unroll
        for (int j = 0; j < 4; ++j) {
            const float* a4 = acc[i*4 + j];
            const int colg  = n0 + wn + j*8 + 2*qcol;
            const float2 bv = *reinterpret_cast<const float2*>(bias + colg);
            #pragma unroll
            for (int half = 0; half < 2; ++half) {
                const int m = m0 + wm + i*16 + qrow + half*8;
                float2 o;
                o.x = a4[half*2 + 0] + bv.x;
                o.y = a4[half*2 + 1] + bv.y;
                size_t idx;
                if (SCATTER) {
                    const int b = m >> 11;
                    const int s = m & (NS - 1);
                    const int h = colg >> 6;
                    const int hd = colg & 63;
                    idx = (((size_t)(b*NH + h))*NS + s)*NHD + hd;
                } else {
                    idx = (size_t)m * N + colg;
                }
                *reinterpret_cast<float2*>(C + idx) = o;
            }
        }
    }
}

// ---------------------------------------------------------------------------
// Tensor-core flash attention (tf32 mma.sync), causal.
// R7: single-tf32 K (no hi/lo split), register double-buffered K/V prefetch,
// vectorized K staging, fully-masked warp-tiles skipped, 2 CTAs/SM pinned.
// smem: 88064 B dynamic.
// ---------------------------------------------------------------------------
#define AQ_STR   68
#define AP_STR   36
#define OFF_Q    0              // 128*68 = 8704
#define OFF_K    8704           // 64*68  = 4352
#define OFF_VT   13056          // 64*68  = 4352
#define OFF_P    17408          // 8*16*36 = 4608
#define SMEM_WORDS 22016        // *4 = 88064 B

__global__ void __launch_bounds__(256, 2)
attn_tc(const float* __restrict__ Q, const float* __restrict__ K,
        const float* __restrict__ V, float* __restrict__ O)
{
    extern __shared__ uint32_t sm[];
    uint32_t* sQ  = sm + OFF_Q;
    uint32_t* sK  = sm + OFF_K;
    uint32_t* sVt = sm + OFF_VT;

    const int tid  = threadIdx.x;
    const int wid  = tid >> 5;
    const int lane = tid & 31;
    const int qrow = lane >> 2;   // 0..7
    const int qcol = lane & 3;    // 0..3
    const int wm   = wid * 16;    // warp's row base within the 128-row tile

    const int qt = (NS/128 - 1) - blockIdx.x;   // largest-work tiles first
    const int h  = blockIdx.y;
    const int b  = blockIdx.z;
    const int bh = b*NH + h;

    const float* Qb = Q + (size_t)bh * NS * NHD;
    const float* Kb = K + (size_t)bh * NS * NHD;
    const float* Vb = V + (size_t)bh * NS * NHD;

    // K staging mapping: 4 passes of (16 rows x 64 cols)
    const int kr = tid >> 4;         // 0..15
    const int kc = (tid & 15) * 4;   // 0..60
    // V-transpose mapping: thread owns one key column, 16 d's
    const int vkey = tid & 63;
    const int vdg  = (tid >> 6) * 16;

    // ---- load Q tile as tf32, [row][d] ----
    #pragma unroll
    for (int p = 0; p < 8; ++p) {
        int lin = tid + 256*p;
        int r = lin >> 4, c = (lin & 15) * 4;
        float4 qv = *reinterpret_cast<const float4*>(
            Qb + (size_t)(qt*128 + r)*NHD + c);
        uint32_t* d = &sQ[r * AQ_STR + c];
        d[0] = cvt_tf32(qv.x);
        d[1] = cvt_tf32(qv.y);
        d[2] = cvt_tf32(qv.z);
        d[3] = cvt_tf32(qv.w);
    }

    float o[8][4];
    #pragma unroll
    for (int nt = 0; nt < 8; ++nt)
        #pragma unroll
        for (int e = 0; e < 4; ++e) o[nt][e] = 0.f;
    float mrow[2] = {-1e30f, -1e30f};
    float lrow[2] = {0.f, 0.f};

    const int jmax = 2*qt + 1;

    // ---- prefetch K/V tile j=0 into registers ----
    float4 kreg[4], vreg[4];
    #pragma unroll
    for (int p = 0; p < 4; ++p)
        kreg[p] = *reinterpret_cast<const float4*>(
            Kb + (size_t)(kr + p*16)*NHD + kc);
    #pragma unroll
    for (int g = 0; g < 4; ++g)
        vreg[g] = *reinterpret_cast<const float4*>(
            Vb + (size_t)vkey*NHD + vdg + g*4);

    for (int j = 0; j <= jmax; ++j) {
        __syncthreads();   // previous iteration done with sK/sVt

        // ---- stage K tile [key][d] (vectorized) ----
        #pragma unroll
        for (int p = 0; p < 4; ++p) {
            uint4 t;
            t.x = cvt_tf32(kreg[p].x);
            t.y = cvt_tf32(kreg[p].y);
            t.z = cvt_tf32(kreg[p].z);
            t.w = cvt_tf32(kreg[p].w);
            *reinterpret_cast<uint4*>(&sK[(kr + p*16) * AQ_STR + kc]) = t;
        }
        // ---- stage V tile transposed: sVt[d][key] ----
        #pragma unroll
        for (int g = 0; g < 4; ++g) {
            float f[4] = {vreg[g].x, vreg[g].y, vreg[g].z, vreg[g].w};
            #pragma unroll
            for (int e = 0; e < 4; ++e)
                sVt[(vdg + g*4 + e) * AQ_STR + vkey] = cvt_tf32(f[e]);
        }

        // ---- prefetch tile j+1 (overlaps compute below) ----
        if (j < jmax) {
            const size_t rb = (size_t)(j + 1) * 64;
            #pragma unroll
            for (int p = 0; p < 4; ++p)
                kreg[p] = *reinterpret_cast<const float4*>(
                    Kb + (rb + kr + p*16)*NHD + kc);
            #pragma unroll
            for (int g = 0; g < 4; ++g)
                vreg[g] = *reinterpret_cast<const float4*>(
                    Vb + (rb + vkey)*NHD + vdg + g*4);
        }

        __syncthreads();

        // warps whose rows are entirely above this key tile are fully masked
        const bool active = (j*64 <= qt*128 + wm + 15);
        if (active) {
            // ---- S = Q @ K^T (single tf32) ----
            float s[8][4];
            #pragma unroll
            for (int nt = 0; nt < 8; ++nt)
                #pragma unroll
                for (int e = 0; e < 4; ++e) s[nt][e] = 0.f;

            #pragma unroll
            for (int ks = 0; ks < 8; ++ks) {
                const uint32_t* qp = &sQ[(wm + qrow) * AQ_STR + ks*8 + qcol];
                uint32_t a0 = qp[0], a1 = qp[8*AQ_STR], a2 = qp[4], a3 = qp[8*AQ_STR + 4];
                #pragma unroll
                for (int nt = 0; nt < 8; ++nt) {
                    const int off = (nt*8 + qrow) * AQ_STR + ks*8 + qcol;
                    mma_tf32(s[nt], a0, a1, a2, a3, sK[off], sK[off + 4]);
                }
            }

            // ---- online softmax (per lane: 2 rows) ----
            const bool need_mask = (j >= 2*qt);
            #pragma unroll
            for (int r = 0; r < 2; ++r) {
                const int rowg = qt*128 + wm + qrow + r*8;
                float mx = -1e30f;
                #pragma unroll
                for (int nt = 0; nt < 8; ++nt) {
                    const int colg = j*64 + nt*8 + 2*qcol;
                    float v0 = s[nt][r*2 + 0] * SCALE_F;
                    float v1 = s[nt][r*2 + 1] * SCALE_F;
                    if (need_mask) {
                        if (colg     > rowg) v0 = -1e30f;
                        if (colg + 1 > rowg) v1 = -1e30f;
                    }
                    s[nt][r*2 + 0] = v0;
                    s[nt][r*2 + 1] = v1;
                    mx = fmaxf(mx, fmaxf(v0, v1));
                }
                mx = fmaxf(mx, __shfl_xor_sync(0xffffffffu, mx, 1));
                mx = fmaxf(mx, __shfl_xor_sync(0xffffffffu, mx, 2));
                const float mn    = fmaxf(mrow[r], mx);
                const float alpha = __expf(mrow[r] - mn);
                mrow[r] = mn;
                float ls = 0.f;
                #pragma unroll
                for (int nt = 0; nt < 8; ++nt) {
                    float p0 = __expf(s[nt][r*2 + 0] - mn);
                    float p1 = __expf(s[nt][r*2 + 1] - mn);
                    s[nt][r*2 + 0] = p0;
                    s[nt][r*2 + 1] = p1;
                    ls += p0 + p1;
                }
                ls += __shfl_xor_sync(0xffffffffu, ls, 1);
                ls += __shfl_xor_sync(0xffffffffu, ls, 2);
                lrow[r] = lrow[r]*alpha + ls;
                #pragma unroll
                for (int nt = 0; nt < 8; ++nt) {
                    o[nt][r*2 + 0] *= alpha;
                    o[nt][r*2 + 1] *= alpha;
                }
            }

            // ---- O += P @ V via per-warp staging (two 32-key halves) ----
            uint32_t* sPw = sm + OFF_P + wid * (16 * AP_STR);
            #pragma unroll
            for (int kh = 0; kh < 2; ++kh) {
                __syncwarp();
                #pragma unroll
                for (int t = 0; t < 4; ++t) {
                    const int nt = kh*4 + t;
                    const int lc = t*8 + 2*qcol;
                    sPw[qrow * AP_STR + lc]           = cvt_tf32(s[nt][0]);
                    sPw[qrow * AP_STR + lc + 1]       = cvt_tf32(s[nt][1]);
                    sPw[(qrow + 8) * AP_STR + lc]     = cvt_tf32(s[nt][2]);
                    sPw[(qrow + 8) * AP_STR + lc + 1] = cvt_tf32(s[nt][3]);
                }
                __syncwarp();
                #pragma unroll
                for (int ks = 0; ks < 4; ++ks) {
                    const uint32_t* p0 = &sPw[qrow * AP_STR + ks*8 + qcol];
                    const uint32_t* p1 = &sPw[(qrow + 8) * AP_STR + ks*8 + qcol];
                    uint32_t a0 = p0[0], a1 = p1[0], a2 = p0[4], a3 = p1[4];
                    #pragma unroll
                    for (int nt = 0; nt < 8; ++nt) {
                        const int off = (nt*8 + qrow) * AQ_STR + kh*32 + ks*8 + qcol;
                        mma_tf32(o[nt], a0, a1, a2, a3, sVt[off], sVt[off + 4]);
                    }
                }
            }
        }
    }

    // ---- normalize + write [B,S,D] ----
    #pragma unroll
    for (int r = 0; r < 2; ++r) {
        const float inv = 1.0f / lrow[r];
        const int rowg = qt*128 + wm + qrow + r*8;
        #pragma unroll
        for (int nt = 0; nt < 8; ++nt) {
            const int col = h*NHD + nt*8 + 2*qcol;
            float2 ov;
            ov.x = o[nt][r*2 + 0] * inv;
            ov.y = o[nt][r*2 + 1] * inv;
            *reinterpret_cast<float2*>(
                O + ((size_t)b*NS + rowg)*ND + col) = ov;
        }
    }
}

// ---------------------------------------------------------------------------
extern "C" void kernel_launch(void* const* d_in, const int* in_sizes, int n_in,
                              void* d_out, int out_size)
{
    const float* x  = (const float*)d_in[0];
    const float* wq = (const float*)d_in[1];
    const float* bq = (const float*)d_in[2];
    const float* wk = (const float*)d_in[3];
    const float* bk = (const float*)d_in[4];
    const float* wv = (const float*)d_in[5];
    const float* bv = (const float*)d_in[6];
    const float* wo = (const float*)d_in[7];
    const float* bo = (const float*)d_in[8];
    float* out = (float*)d_out;

    float *q, *k, *v, *att;
    cudaGetSymbolAddress((void**)&q,   g_q);
    cudaGetSymbolAddress((void**)&k,   g_k);
    cudaGetSymbolAddress((void**)&v,   g_v);
    cudaGetSymbolAddress((void**)&att, g_att);

    static bool attr_done = false;
    if (!attr_done) {
        cudaFuncSetAttribute(attn_tc,
            cudaFuncAttributeMaxDynamicSharedMemorySize, SMEM_WORDS * 4);
        attr_done = true;
    }

    dim3 ggrid(ND/128, NM/128);   // (8, 32)
    gemm_tc<true ><<<ggrid, 256>>>(x,   wq, bq, q);
    gemm_tc<true ><<<ggrid, 256>>>(x,   wk, bk, k);
    gemm_tc<true ><<<ggrid, 256>>>(x,   wv, bv, v);

    dim3 agrid(NS/128, NH, NB);   // (16, 16, 2)
    attn_tc<<<agrid, 256, SMEM_WORDS * 4>>>(q, k, v, att);

    gemm_tc<false><<<ggrid, 256>>>(att, wo, bo, out);
}